// round 1
// baseline (speedup 1.0000x reference)
#include <cuda_runtime.h>
#include <math.h>

#define NB 256      // batch / steps
#define ND 512      // D
#define NH 2048     // H
#define NS 32768    // slots
#define NSPLIT 8
#define KCH (NS / NSPLIT)   // 4096

// ---------------- static device scratch (no allocations allowed) ----------------
__device__ float g_K[NB * ND];          // key projections
__device__ float g_WV[NB * ND];         // value projections
__device__ float g_G[NB * NB];          // Gram: G[i][t] = K_i . K_t
__device__ float g_E[NB * NS];          // base scores, then exp(score - m_i) in-place
__device__ float g_m[NB];               // per-step base column max
__device__ float g_Z0[NB];              // base softmax denominators
__device__ float g_part[NSPLIT * NB * ND]; // split-K partials for R0
__device__ int   g_slots[NB];           // argmax slot per step
__device__ float g_merged[NB * 2 * ND]; // [s_i, read_val]
__device__ float g_H1[NB * NH];         // MLP hidden

// ---------------- generic tiled fp32 GEMM: C[M,N] = A[M,K] * B[N,K]^T (+bias)(+relu) ----------------
__global__ void __launch_bounds__(256) gemm_nt_kernel(
    const float* __restrict__ A, const float* __restrict__ B, float* __restrict__ C,
    int M, int N, int Kd, const float* __restrict__ bias, int doRelu)
{
    __shared__ __align__(16) float As[16][68];
    __shared__ __align__(16) float Bs[16][68];
    const int tid = threadIdx.x;
    const int tx = tid & 15, ty = tid >> 4;
    const int bm0 = blockIdx.y * 64, bn0 = blockIdx.x * 64;
    const int lr = tid >> 2;
    const int lq = (tid & 3) * 4;
    const float* Ap = A + (size_t)(bm0 + lr) * Kd + lq;
    const float* Bp = B + (size_t)(bn0 + lr) * Kd + lq;
    float c[4][4] = {};
    for (int k0 = 0; k0 < Kd; k0 += 16) {
        float4 av = *(const float4*)(Ap + k0);
        float4 bv = *(const float4*)(Bp + k0);
        __syncthreads();
        As[lq + 0][lr] = av.x; As[lq + 1][lr] = av.y;
        As[lq + 2][lr] = av.z; As[lq + 3][lr] = av.w;
        Bs[lq + 0][lr] = bv.x; Bs[lq + 1][lr] = bv.y;
        Bs[lq + 2][lr] = bv.z; Bs[lq + 3][lr] = bv.w;
        __syncthreads();
        #pragma unroll
        for (int k = 0; k < 16; k++) {
            float4 a = *(const float4*)&As[k][ty * 4];
            float4 b = *(const float4*)&Bs[k][tx * 4];
            c[0][0] += a.x * b.x; c[0][1] += a.x * b.y; c[0][2] += a.x * b.z; c[0][3] += a.x * b.w;
            c[1][0] += a.y * b.x; c[1][1] += a.y * b.y; c[1][2] += a.y * b.z; c[1][3] += a.y * b.w;
            c[2][0] += a.z * b.x; c[2][1] += a.z * b.y; c[2][2] += a.z * b.z; c[2][3] += a.z * b.w;
            c[3][0] += a.w * b.x; c[3][1] += a.w * b.y; c[3][2] += a.w * b.z; c[3][3] += a.w * b.w;
        }
    }
    float4 bias4 = make_float4(0.f, 0.f, 0.f, 0.f);
    if (bias) bias4 = *(const float4*)&bias[bn0 + tx * 4];
    #pragma unroll
    for (int a = 0; a < 4; a++) {
        float4 o;
        o.x = c[a][0] + bias4.x;
        o.y = c[a][1] + bias4.y;
        o.z = c[a][2] + bias4.z;
        o.w = c[a][3] + bias4.w;
        if (doRelu) {
            o.x = fmaxf(o.x, 0.f); o.y = fmaxf(o.y, 0.f);
            o.z = fmaxf(o.z, 0.f); o.w = fmaxf(o.w, 0.f);
        }
        *(float4*)&C[(size_t)(bm0 + ty * 4 + a) * N + bn0 + tx * 4] = o;
    }
}

// ---------------- per-step-column max, then exp in-place + sum ----------------
__global__ void __launch_bounds__(256) colmax_exp_kernel()
{
    const int i = blockIdx.x;
    const int tid = threadIdx.x;
    __shared__ float red[256];
    float4* row = (float4*)(g_E + (size_t)i * NS);
    float mx = -1e30f;
    for (int q = tid; q < NS / 4; q += 256) {
        float4 v = row[q];
        mx = fmaxf(mx, fmaxf(fmaxf(v.x, v.y), fmaxf(v.z, v.w)));
    }
    red[tid] = mx;
    __syncthreads();
    for (int s = 128; s; s >>= 1) {
        if (tid < s) red[tid] = fmaxf(red[tid], red[tid + s]);
        __syncthreads();
    }
    const float m = red[0];
    __syncthreads();
    if (tid == 0) g_m[i] = m;
    float sum = 0.f;
    for (int q = tid; q < NS / 4; q += 256) {
        float4 v = row[q];
        v.x = expf(v.x - m); v.y = expf(v.y - m);
        v.z = expf(v.z - m); v.w = expf(v.w - m);
        sum += (v.x + v.y) + (v.z + v.w);
        row[q] = v;
    }
    __syncthreads();
    red[tid] = sum;
    __syncthreads();
    for (int s = 128; s; s >>= 1) {
        if (tid < s) red[tid] += red[tid + s];
        __syncthreads();
    }
    if (tid == 0) g_Z0[i] = red[0];
}

// ---------------- split-K GEMM: part[z][i][d] = sum_{j in chunk z} E[i][j] * MV[j][d] ----------------
__global__ void __launch_bounds__(256) gemm_r0_kernel(const float* __restrict__ MV)
{
    __shared__ __align__(16) float As[16][68];
    __shared__ __align__(16) float Bs[16][68];
    const int tid = threadIdx.x;
    const int tx = tid & 15, ty = tid >> 4;
    const int bm0 = blockIdx.y * 64;          // i tile
    const int bn0 = blockIdx.x * 64;          // d tile
    const int kbase = blockIdx.z * KCH;       // j chunk
    const int lr = tid >> 2;
    const int lq = (tid & 3) * 4;
    const int jr = tid >> 4;                  // B: 16 rows (j)
    const int dq = (tid & 15) * 4;            // B: 64 cols (d) as float4
    float c[4][4] = {};
    for (int k0 = 0; k0 < KCH; k0 += 16) {
        float4 av = *(const float4*)(g_E + (size_t)(bm0 + lr) * NS + kbase + k0 + lq);
        float4 bv = *(const float4*)(MV + (size_t)(kbase + k0 + jr) * ND + bn0 + dq);
        __syncthreads();
        As[lq + 0][lr] = av.x; As[lq + 1][lr] = av.y;
        As[lq + 2][lr] = av.z; As[lq + 3][lr] = av.w;
        *(float4*)&Bs[jr][dq] = bv;
        __syncthreads();
        #pragma unroll
        for (int k = 0; k < 16; k++) {
            float4 a = *(const float4*)&As[k][ty * 4];
            float4 b = *(const float4*)&Bs[k][tx * 4];
            c[0][0] += a.x * b.x; c[0][1] += a.x * b.y; c[0][2] += a.x * b.z; c[0][3] += a.x * b.w;
            c[1][0] += a.y * b.x; c[1][1] += a.y * b.y; c[1][2] += a.y * b.z; c[1][3] += a.y * b.w;
            c[2][0] += a.z * b.x; c[2][1] += a.z * b.y; c[2][2] += a.z * b.z; c[2][3] += a.z * b.w;
            c[3][0] += a.w * b.x; c[3][1] += a.w * b.y; c[3][2] += a.w * b.z; c[3][3] += a.w * b.w;
        }
    }
    float* out = g_part + (size_t)blockIdx.z * NB * ND;
    #pragma unroll
    for (int a = 0; a < 4; a++) {
        float4 o = make_float4(c[a][0], c[a][1], c[a][2], c[a][3]);
        *(float4*)&out[(size_t)(bm0 + ty * 4 + a) * ND + bn0 + tx * 4] = o;
    }
}

// ---------------- the only sequential part: 256 argmax decisions ----------------
// Scans E row i with substitution at modified slots (writer table in smem).
__global__ void __launch_bounds__(1024) seq_kernel()
{
    __shared__ unsigned int wBytes[NS / 4];   // 32KB: writer step per slot (u8)
    __shared__ unsigned int mask[NS / 32];    // 4KB:  modified bitmask
    __shared__ float ge[NB];                  // corrected exp values for this step
    __shared__ float sv[32];
    __shared__ int si[32];
    const int tid = threadIdx.x;
    for (int q = tid; q < NS / 4; q += 1024) wBytes[q] = 0u;
    for (int q = tid; q < NS / 32; q += 1024) mask[q] = 0u;
    __syncthreads();
    for (int i = 0; i < NB; i++) {
        const float mi = g_m[i];
        if (tid < NB) ge[tid] = expf(g_G[i * NB + tid] - mi);
        __syncthreads();
        const float4* row = (const float4*)(g_E + (size_t)i * NS);
        float best = -1e30f;
        int bidx = NS;
        #pragma unroll
        for (int k = 0; k < 8; k++) {
            const int q = tid + k * 1024;
            float4 v = row[q];
            const unsigned int w4 = wBytes[q];
            const unsigned int mw = mask[q >> 3];
            const int mb = (q & 7) * 4;
            float vals[4] = {v.x, v.y, v.z, v.w};
            #pragma unroll
            for (int u = 0; u < 4; u++) {
                float val = vals[u];
                if ((mw >> (mb + u)) & 1u) val = ge[(w4 >> (8 * u)) & 255u];
                const int jj = q * 4 + u;
                if (val > best || (val == best && jj < bidx)) { best = val; bidx = jj; }
            }
        }
        const unsigned fm = 0xffffffffu;
        #pragma unroll
        for (int off = 16; off; off >>= 1) {
            float ov = __shfl_down_sync(fm, best, off);
            int oi = __shfl_down_sync(fm, bidx, off);
            if (ov > best || (ov == best && oi < bidx)) { best = ov; bidx = oi; }
        }
        if ((tid & 31) == 0) { sv[tid >> 5] = best; si[tid >> 5] = bidx; }
        __syncthreads();
        if (tid < 32) {
            best = sv[tid]; bidx = si[tid];
            #pragma unroll
            for (int off = 16; off; off >>= 1) {
                float ov = __shfl_down_sync(fm, best, off);
                int oi = __shfl_down_sync(fm, bidx, off);
                if (ov > best || (ov == best && oi < bidx)) { best = ov; bidx = oi; }
            }
            if (tid == 0) {
                g_slots[i] = bidx;
                ((unsigned char*)wBytes)[bidx] = (unsigned char)i;
                atomicOr(&mask[bidx >> 5], 1u << (bidx & 31));
            }
        }
        __syncthreads();
    }
}

// ---------------- parallel (per-step) read_val correction + merge ----------------
__global__ void __launch_bounds__(512) passB_kernel(const float* __restrict__ S,
                                                    const float* __restrict__ MV)
{
    const int i = blockIdx.x;
    const int tid = threadIdx.x;
    __shared__ int sl[NB];
    __shared__ float e0s[NB], e1s[NB], zar[NB];
    __shared__ unsigned char lastf[NB];
    if (tid < NB) sl[tid] = g_slots[tid];
    __syncthreads();
    const float mi = g_m[i];
    if (tid < NB) {
        float z = 0.f;
        unsigned char lf = 0;
        if (tid < i) {
            const int t = tid;
            const int s = sl[t];
            bool last = true;
            for (int t2 = t + 1; t2 < i; t2++)
                if (sl[t2] == s) { last = false; break; }
            if (last) {
                lf = 1;
                const float e0 = g_E[(size_t)i * NS + s];
                const float e1 = expf(g_G[i * NB + t] - mi);
                e0s[t] = e0; e1s[t] = e1;
                z = e1 - e0;
            }
        }
        lastf[tid] = lf;
        zar[tid] = z;
    }
    __syncthreads();
    for (int s = 128; s; s >>= 1) {
        if (tid < s) zar[tid] += zar[tid + s];
        __syncthreads();
    }
    const float Z = g_Z0[i] + zar[0];
    const int d = tid;  // 512 threads = 512 dims
    float r = 0.f;
    #pragma unroll
    for (int sk = 0; sk < NSPLIT; sk++) r += g_part[(size_t)sk * NB * ND + (size_t)i * ND + d];
    for (int t = 0; t < i; t++) {
        if (lastf[t]) {
            r += e1s[t] * g_WV[(size_t)t * ND + d] - e0s[t] * MV[(size_t)sl[t] * ND + d];
        }
    }
    g_merged[(size_t)i * (2 * ND) + d] = S[(size_t)i * ND + d];
    g_merged[(size_t)i * (2 * ND) + ND + d] = r / Z;
}

// ---------------- launch ----------------
extern "C" void kernel_launch(void* const* d_in, const int* in_sizes, int n_in,
                              void* d_out, int out_size)
{
    (void)in_sizes; (void)n_in; (void)out_size;
    const float* S  = (const float*)d_in[0];
    const float* MK = (const float*)d_in[1];
    const float* MV = (const float*)d_in[2];
    const float* Wk = (const float*)d_in[3];
    const float* bk = (const float*)d_in[4];
    const float* Wv = (const float*)d_in[5];
    const float* bv = (const float*)d_in[6];
    const float* W1 = (const float*)d_in[7];
    const float* b1 = (const float*)d_in[8];
    const float* W2 = (const float*)d_in[9];
    const float* b2 = (const float*)d_in[10];
    float* out = (float*)d_out;

    float *pK, *pWV, *pG, *pE, *pMerged, *pH1;
    cudaGetSymbolAddress((void**)&pK, g_K);
    cudaGetSymbolAddress((void**)&pWV, g_WV);
    cudaGetSymbolAddress((void**)&pG, g_G);
    cudaGetSymbolAddress((void**)&pE, g_E);
    cudaGetSymbolAddress((void**)&pMerged, g_merged);
    cudaGetSymbolAddress((void**)&pH1, g_H1);

    const dim3 blk(256);
    // K = S @ Wk^T + bk ; WV = S @ Wv^T + bv
    gemm_nt_kernel<<<dim3(ND / 64, NB / 64), blk>>>(S, Wk, pK, NB, ND, ND, bk, 0);
    gemm_nt_kernel<<<dim3(ND / 64, NB / 64), blk>>>(S, Wv, pWV, NB, ND, ND, bv, 0);
    // G = K @ K^T
    gemm_nt_kernel<<<dim3(NB / 64, NB / 64), blk>>>(pK, pK, pG, NB, NB, ND, nullptr, 0);
    // base scores: E[i][j] = K_i . mem_keys_j
    gemm_nt_kernel<<<dim3(NS / 64, NB / 64), blk>>>(pK, MK, pE, NB, NS, ND, nullptr, 0);
    // column max, exp in-place, Z0
    colmax_exp_kernel<<<NB, 256>>>();
    // R0 partials = E @ mem_vals (split-K)
    gemm_r0_kernel<<<dim3(ND / 64, NB / 64, NSPLIT), blk>>>(MV);
    // sequential argmax chain
    seq_kernel<<<1, 1024>>>();
    // per-step corrections -> merged = [s_i, read_val]
    passB_kernel<<<NB, 512>>>(S, MV);
    // MLP: relu(merged @ W1^T + b1) @ W2^T + b2
    gemm_nt_kernel<<<dim3(NH / 64, NB / 64), blk>>>(pMerged, W1, pH1, NB, NH, 2 * ND, b1, 1);
    gemm_nt_kernel<<<dim3(ND / 64, NB / 64), blk>>>(pH1, W2, out, NB, ND, NH, b2, 0);
}

// round 4
// speedup vs baseline: 1.5487x; 1.5487x over previous
#include <cuda_runtime.h>
#include <math.h>

#define NB 256      // batch / steps
#define ND 512      // D
#define NH 2048     // H
#define NS 32768    // slots
#define RSPLIT 32
#define RCH (NS / RSPLIT)   // 1024
#define CMAX 4096

// ---------------- static device scratch ----------------
__device__ float g_K[NB * ND];
__device__ float g_WV[NB * ND];
__device__ float g_G[NB * NB];
__device__ float g_E[NB * NS];              // raw scores (never overwritten)
__device__ float g_m[NB];
__device__ float g_Z0[NB];
__device__ float g_part[RSPLIT * NB * ND];
__device__ int   g_slots[NB];
__device__ float g_merged[NB * 2 * ND];
__device__ float g_H1[NB * NH];
__device__ unsigned long long g_cand[(size_t)NB * CMAX];
__device__ int g_cand_n[NB];

__device__ __forceinline__ unsigned int fkey(float f) {
    unsigned int u = __float_as_uint(f);
    return u ^ (((unsigned int)((int)u >> 31)) | 0x80000000u);
}

// ---------------- 64x64 tile GEMM (small matrices): C[M,N] = A[M,K] * B[N,K]^T ----------------
__global__ void __launch_bounds__(256) gemm_nt_kernel(
    const float* __restrict__ A, const float* __restrict__ B, float* __restrict__ C,
    int M, int N, int Kd, const float* __restrict__ bias, int doRelu)
{
    __shared__ __align__(16) float As[16][68];
    __shared__ __align__(16) float Bs[16][68];
    const int tid = threadIdx.x;
    const int tx = tid & 15, ty = tid >> 4;
    const int bm0 = blockIdx.y * 64, bn0 = blockIdx.x * 64;
    const int lr = tid >> 2;
    const int lq = (tid & 3) * 4;
    const float* Ap = A + (size_t)(bm0 + lr) * Kd + lq;
    const float* Bp = B + (size_t)(bn0 + lr) * Kd + lq;
    float c[4][4] = {};
    for (int k0 = 0; k0 < Kd; k0 += 16) {
        float4 av = *(const float4*)(Ap + k0);
        float4 bv = *(const float4*)(Bp + k0);
        __syncthreads();
        As[lq + 0][lr] = av.x; As[lq + 1][lr] = av.y;
        As[lq + 2][lr] = av.z; As[lq + 3][lr] = av.w;
        Bs[lq + 0][lr] = bv.x; Bs[lq + 1][lr] = bv.y;
        Bs[lq + 2][lr] = bv.z; Bs[lq + 3][lr] = bv.w;
        __syncthreads();
        #pragma unroll
        for (int k = 0; k < 16; k++) {
            float4 a = *(const float4*)&As[k][ty * 4];
            float4 b = *(const float4*)&Bs[k][tx * 4];
            c[0][0] += a.x * b.x; c[0][1] += a.x * b.y; c[0][2] += a.x * b.z; c[0][3] += a.x * b.w;
            c[1][0] += a.y * b.x; c[1][1] += a.y * b.y; c[1][2] += a.y * b.z; c[1][3] += a.y * b.w;
            c[2][0] += a.z * b.x; c[2][1] += a.z * b.y; c[2][2] += a.z * b.z; c[2][3] += a.z * b.w;
            c[3][0] += a.w * b.x; c[3][1] += a.w * b.y; c[3][2] += a.w * b.z; c[3][3] += a.w * b.w;
        }
    }
    float4 bias4 = make_float4(0.f, 0.f, 0.f, 0.f);
    if (bias) bias4 = *(const float4*)&bias[bn0 + tx * 4];
    #pragma unroll
    for (int a = 0; a < 4; a++) {
        float4 o;
        o.x = c[a][0] + bias4.x;
        o.y = c[a][1] + bias4.y;
        o.z = c[a][2] + bias4.z;
        o.w = c[a][3] + bias4.w;
        if (doRelu) {
            o.x = fmaxf(o.x, 0.f); o.y = fmaxf(o.y, 0.f);
            o.z = fmaxf(o.z, 0.f); o.w = fmaxf(o.w, 0.f);
        }
        *(float4*)&C[(size_t)(bm0 + ty * 4 + a) * N + bn0 + tx * 4] = o;
    }
}

// ---------------- 128x128 tile NT GEMM (E = K @ MK^T) ----------------
#define FMA8x8(kk)                                                              \
    {                                                                           \
        float4 t0 = *(const float4*)&As[buf][kk][ty * 4];                       \
        float4 t1 = *(const float4*)&As[buf][kk][ty * 4 + 64];                  \
        float4 t2 = *(const float4*)&Bs[buf][kk][tx * 4];                       \
        float4 t3 = *(const float4*)&Bs[buf][kk][tx * 4 + 64];                  \
        float ar[8] = {t0.x, t0.y, t0.z, t0.w, t1.x, t1.y, t1.z, t1.w};         \
        float br[8] = {t2.x, t2.y, t2.z, t2.w, t3.x, t3.y, t3.z, t3.w};         \
        _Pragma("unroll")                                                       \
        for (int m = 0; m < 8; m++)                                             \
            _Pragma("unroll")                                                   \
            for (int n = 0; n < 8; n++) acc[m][n] += ar[m] * br[n];             \
    }

__global__ void __launch_bounds__(256) gemm_nt_128(
    const float* __restrict__ A, const float* __restrict__ B, float* __restrict__ C,
    int N, int Kd)
{
    __shared__ __align__(16) float As[2][8][136];
    __shared__ __align__(16) float Bs[2][8][136];
    const int tid = threadIdx.x;
    const int bm0 = blockIdx.y * 128, bn0 = blockIdx.x * 128;
    const int lr = tid >> 1;
    const int lk = (tid & 1) * 4;
    const float* Ap = A + (size_t)(bm0 + lr) * Kd + lk;
    const float* Bp = B + (size_t)(bn0 + lr) * Kd + lk;
    const int tx = tid & 15, ty = tid >> 4;
    float acc[8][8] = {};
    int buf = 0;
    {
        float4 a = *(const float4*)Ap;
        float4 b = *(const float4*)Bp;
        As[0][lk + 0][lr] = a.x; As[0][lk + 1][lr] = a.y;
        As[0][lk + 2][lr] = a.z; As[0][lk + 3][lr] = a.w;
        Bs[0][lk + 0][lr] = b.x; Bs[0][lk + 1][lr] = b.y;
        Bs[0][lk + 2][lr] = b.z; Bs[0][lk + 3][lr] = b.w;
    }
    __syncthreads();
    for (int k0 = 8; k0 <= Kd; k0 += 8) {
        float4 an, bn;
        if (k0 < Kd) {
            an = *(const float4*)(Ap + k0);
            bn = *(const float4*)(Bp + k0);
        }
        #pragma unroll
        for (int kk = 0; kk < 8; kk++) FMA8x8(kk)
        if (k0 < Kd) {
            buf ^= 1;
            As[buf][lk + 0][lr] = an.x; As[buf][lk + 1][lr] = an.y;
            As[buf][lk + 2][lr] = an.z; As[buf][lk + 3][lr] = an.w;
            Bs[buf][lk + 0][lr] = bn.x; Bs[buf][lk + 1][lr] = bn.y;
            Bs[buf][lk + 2][lr] = bn.z; Bs[buf][lk + 3][lr] = bn.w;
            __syncthreads();
        }
    }
    #pragma unroll
    for (int m = 0; m < 8; m++) {
        int r = bm0 + ty * 4 + (m & 3) + (m >> 2) * 64;
        *(float4*)&C[(size_t)r * N + bn0 + tx * 4] =
            make_float4(acc[m][0], acc[m][1], acc[m][2], acc[m][3]);
        *(float4*)&C[(size_t)r * N + bn0 + tx * 4 + 64] =
            make_float4(acc[m][4], acc[m][5], acc[m][6], acc[m][7]);
    }
}

// ---------------- 128x128 split-K NN GEMM: part[z] = exp(E - m) @ MV ----------------
__global__ void __launch_bounds__(256) gemm_nn_r0(const float* __restrict__ MV)
{
    __shared__ __align__(16) float As[2][8][136];
    __shared__ __align__(16) float Bs[2][8][132];
    const int tid = threadIdx.x;
    const int bn0 = blockIdx.x * 128;      // d tile
    const int bm0 = blockIdx.y * 128;      // i tile
    const int kb = blockIdx.z * RCH;       // slot chunk
    const int lr = tid >> 1;
    const int lk = (tid & 1) * 4;
    const int kr = tid >> 5;               // 0..7
    const int nq = (tid & 31) * 4;         // 0..124
    const float mval = g_m[bm0 + lr];
    const float* Ap = g_E + (size_t)(bm0 + lr) * NS + kb + lk;
    const float* Bp = MV + (size_t)(kb + kr) * ND + bn0 + nq;
    const int tx = tid & 15, ty = tid >> 4;
    float acc[8][8] = {};
    int buf = 0;
    {
        float4 a = *(const float4*)Ap;
        float4 b = *(const float4*)Bp;
        As[0][lk + 0][lr] = expf(a.x - mval); As[0][lk + 1][lr] = expf(a.y - mval);
        As[0][lk + 2][lr] = expf(a.z - mval); As[0][lk + 3][lr] = expf(a.w - mval);
        *(float4*)&Bs[0][kr][nq] = b;
    }
    __syncthreads();
    for (int k0 = 8; k0 <= RCH; k0 += 8) {
        float4 an, bn;
        if (k0 < RCH) {
            an = *(const float4*)(Ap + k0);
            bn = *(const float4*)(Bp + (size_t)k0 * ND);
        }
        #pragma unroll
        for (int kk = 0; kk < 8; kk++) FMA8x8(kk)
        if (k0 < RCH) {
            buf ^= 1;
            As[buf][lk + 0][lr] = expf(an.x - mval); As[buf][lk + 1][lr] = expf(an.y - mval);
            As[buf][lk + 2][lr] = expf(an.z - mval); As[buf][lk + 3][lr] = expf(an.w - mval);
            *(float4*)&Bs[buf][kr][nq] = bn;
            __syncthreads();
        }
    }
    float* out = g_part + (size_t)blockIdx.z * NB * ND;
    #pragma unroll
    for (int m = 0; m < 8; m++) {
        int r = bm0 + ty * 4 + (m & 3) + (m >> 2) * 64;
        *(float4*)&out[(size_t)r * ND + bn0 + tx * 4] =
            make_float4(acc[m][0], acc[m][1], acc[m][2], acc[m][3]);
        *(float4*)&out[(size_t)r * ND + bn0 + tx * 4 + 64] =
            make_float4(acc[m][4], acc[m][5], acc[m][6], acc[m][7]);
    }
}

// ---------------- per-row max + softmax denominator (no writeback) ----------------
__global__ void __launch_bounds__(256) colmax_kernel()
{
    const int i = blockIdx.x;
    const int tid = threadIdx.x;
    __shared__ float red[256];
    const float4* row = (const float4*)(g_E + (size_t)i * NS);
    float mx = -1e30f;
    for (int q = tid; q < NS / 4; q += 256) {
        float4 v = row[q];
        mx = fmaxf(mx, fmaxf(fmaxf(v.x, v.y), fmaxf(v.z, v.w)));
    }
    red[tid] = mx;
    __syncthreads();
    for (int s = 128; s; s >>= 1) {
        if (tid < s) red[tid] = fmaxf(red[tid], red[tid + s]);
        __syncthreads();
    }
    const float m = red[0];
    __syncthreads();
    if (tid == 0) g_m[i] = m;
    float sum = 0.f;
    for (int q = tid; q < NS / 4; q += 256) {
        float4 v = row[q];
        sum += (expf(v.x - m) + expf(v.y - m)) + (expf(v.z - m) + expf(v.w - m));
    }
    red[tid] = sum;
    __syncthreads();
    for (int s = 128; s; s >>= 1) {
        if (tid < s) red[tid] += red[tid + s];
        __syncthreads();
    }
    if (tid == 0) g_Z0[i] = red[0];
}

// ---------------- per-row candidate extraction: superset of top-256 base values ----------------
__global__ void __launch_bounds__(256) topk_kernel()
{
    const int i = blockIdx.x;
    const int tid = threadIdx.x;
    __shared__ unsigned int hist[4096];
    __shared__ unsigned int csum[256];
    __shared__ int s_thr;
    __shared__ int s_cnt;
    for (int q = tid; q < 4096; q += 256) hist[q] = 0;
    if (tid == 0) s_cnt = 0;
    __syncthreads();
    const float* row = g_E + (size_t)i * NS;
    for (int q = tid; q < NS; q += 256)
        atomicAdd(&hist[fkey(row[q]) >> 20], 1u);
    __syncthreads();
    unsigned int s = 0;
    #pragma unroll
    for (int b = 0; b < 16; b++) s += hist[tid * 16 + b];
    csum[tid] = s;
    __syncthreads();
    if (tid == 0) {
        unsigned int run = 0;
        int c = 255;
        for (; c > 0; c--) { if (run + csum[c] >= 256u) break; run += csum[c]; }
        int b = c * 16 + 15;
        for (; b > c * 16; b--) { run += hist[b]; if (run >= 256u) break; }
        if (b == c * 16) run += hist[b];
        s_thr = b;
    }
    __syncthreads();
    const unsigned int thr = ((unsigned int)s_thr) << 20;
    for (int q = tid; q < NS; q += 256) {
        unsigned int k = fkey(row[q]);
        if (k >= thr) {
            int pos = atomicAdd(&s_cnt, 1);
            if (pos < CMAX)
                g_cand[(size_t)i * CMAX + pos] =
                    ((unsigned long long)k << 32) | (unsigned int)(~q);
        }
    }
    __syncthreads();
    if (tid == 0) g_cand_n[i] = s_cnt < CMAX ? s_cnt : CMAX;
}

// ---------------- sequential argmax chain over candidates + writer list ----------------
__global__ void __launch_bounds__(256) seq_kernel()
{
    __shared__ unsigned int mask[NS / 32];    // 4KB modified bitmask
    __shared__ int slotArr[NB];
    __shared__ int writerArr[NB];
    __shared__ unsigned long long wred[8];
    __shared__ int s_cnt, s_found, s_best;
    const int tid = threadIdx.x;
    for (int q = tid; q < NS / 32; q += 256) mask[q] = 0u;
    if (tid == 0) { s_cnt = 0; s_found = -1; }
    __syncthreads();
    for (int i = 0; i < NB; i++) {
        const int cn = g_cand_n[i];
        const unsigned long long* cd = g_cand + (size_t)i * CMAX;
        unsigned long long best = 0ull;
        for (int q = tid; q < cn; q += 256) {
            unsigned long long p = cd[q];
            unsigned int idx = ~(unsigned int)p;
            if (!((mask[idx >> 5] >> (idx & 31)) & 1u))
                best = best > p ? best : p;
        }
        const int cnt = s_cnt;
        if (tid < cnt) {
            float g = g_G[i * NB + writerArr[tid]];
            unsigned long long p =
                ((unsigned long long)fkey(g) << 32) | (unsigned int)(~slotArr[tid]);
            best = best > p ? best : p;
        }
        #pragma unroll
        for (int off = 16; off; off >>= 1) {
            unsigned long long o = __shfl_down_sync(0xffffffffu, best, off);
            best = best > o ? best : o;
        }
        if ((tid & 31) == 0) wred[tid >> 5] = best;
        __syncthreads();
        if (tid < 8) {
            best = wred[tid];
            #pragma unroll
            for (int off = 4; off; off >>= 1) {
                unsigned long long o = __shfl_down_sync(0xffu, best, off);
                best = best > o ? best : o;
            }
            if (tid == 0) s_best = (int)(~(unsigned int)best);
        }
        __syncthreads();
        const int sb = s_best;
        if (tid < cnt && slotArr[tid] == sb) s_found = tid;
        __syncthreads();
        if (tid == 0) {
            g_slots[i] = sb;
            if (s_found >= 0) { writerArr[s_found] = i; s_found = -1; }
            else { slotArr[s_cnt] = sb; writerArr[s_cnt] = i; s_cnt = s_cnt + 1; }
            mask[sb >> 5] |= (1u << (sb & 31));
        }
        __syncthreads();
    }
}

// ---------------- per-step read_val correction + merge ----------------
__global__ void __launch_bounds__(512) passB_kernel(const float* __restrict__ S,
                                                    const float* __restrict__ MV)
{
    const int i = blockIdx.x;
    const int tid = threadIdx.x;
    __shared__ int sl[NB];
    __shared__ float e0s[NB], e1s[NB], zar[NB];
    __shared__ unsigned char lastf[NB];
    if (tid < NB) sl[tid] = g_slots[tid];
    __syncthreads();
    const float mi = g_m[i];
    if (tid < NB) {
        float z = 0.f;
        unsigned char lf = 0;
        if (tid < i) {
            const int t = tid;
            const int s = sl[t];
            bool last = true;
            for (int t2 = t + 1; t2 < i; t2++)
                if (sl[t2] == s) { last = false; break; }
            if (last) {
                lf = 1;
                const float e0 = expf(g_E[(size_t)i * NS + s] - mi);
                const float e1 = expf(g_G[i * NB + t] - mi);
                e0s[t] = e0; e1s[t] = e1;
                z = e1 - e0;
            }
        }
        lastf[tid] = lf;
        zar[tid] = z;
    }
    __syncthreads();
    for (int s = 128; s; s >>= 1) {
        if (tid < s) zar[tid] += zar[tid + s];
        __syncthreads();
    }
    const float Z = g_Z0[i] + zar[0];
    const int d = tid;  // 512 threads = 512 dims
    float r = 0.f;
    #pragma unroll
    for (int sk = 0; sk < RSPLIT; sk++)
        r += g_part[(size_t)sk * NB * ND + (size_t)i * ND + d];
    for (int t = 0; t < i; t++) {
        if (lastf[t]) {
            r += e1s[t] * g_WV[(size_t)t * ND + d] - e0s[t] * MV[(size_t)sl[t] * ND + d];
        }
    }
    g_merged[(size_t)i * (2 * ND) + d] = S[(size_t)i * ND + d];
    g_merged[(size_t)i * (2 * ND) + ND + d] = r / Z;
}

// ---------------- launch ----------------
extern "C" void kernel_launch(void* const* d_in, const int* in_sizes, int n_in,
                              void* d_out, int out_size)
{
    (void)in_sizes; (void)n_in; (void)out_size;
    const float* S  = (const float*)d_in[0];
    const float* MK = (const float*)d_in[1];
    const float* MV = (const float*)d_in[2];
    const float* Wk = (const float*)d_in[3];
    const float* bk = (const float*)d_in[4];
    const float* Wv = (const float*)d_in[5];
    const float* bv = (const float*)d_in[6];
    const float* W1 = (const float*)d_in[7];
    const float* b1 = (const float*)d_in[8];
    const float* W2 = (const float*)d_in[9];
    const float* b2 = (const float*)d_in[10];
    float* out = (float*)d_out;

    float *pK, *pWV, *pG, *pE, *pMerged, *pH1;
    cudaGetSymbolAddress((void**)&pK, g_K);
    cudaGetSymbolAddress((void**)&pWV, g_WV);
    cudaGetSymbolAddress((void**)&pG, g_G);
    cudaGetSymbolAddress((void**)&pE, g_E);
    cudaGetSymbolAddress((void**)&pMerged, g_merged);
    cudaGetSymbolAddress((void**)&pH1, g_H1);

    const dim3 blk(256);
    // projections + Gram
    gemm_nt_kernel<<<dim3(ND / 64, NB / 64), blk>>>(S, Wk, pK, NB, ND, ND, bk, 0);
    gemm_nt_kernel<<<dim3(ND / 64, NB / 64), blk>>>(S, Wv, pWV, NB, ND, ND, bv, 0);
    gemm_nt_kernel<<<dim3(NB / 64, NB / 64), blk>>>(pK, pK, pG, NB, NB, ND, nullptr, 0);
    // base scores E (raw)
    gemm_nt_128<<<dim3(NS / 128, NB / 128), blk>>>(pK, MK, pE, NS, ND);
    // candidates from raw E
    topk_kernel<<<NB, 256>>>();
    // row max + Z0 (no writeback)
    colmax_kernel<<<NB, 256>>>();
    // R0 partials = exp(E - m) @ MV  (split-K, exp on the fly)
    gemm_nn_r0<<<dim3(ND / 128, NB / 128, RSPLIT), blk>>>(MV);
    // sequential argmax chain (candidates + writer list only)
    seq_kernel<<<1, 256>>>();
    // per-step corrections -> merged = [s_i, read_val]
    passB_kernel<<<NB, 512>>>(S, MV);
    // MLP
    gemm_nt_kernel<<<dim3(NH / 64, NB / 64), blk>>>(pMerged, W1, pH1, NB, NH, 2 * ND, b1, 1);
    gemm_nt_kernel<<<dim3(ND / 64, NB / 64), blk>>>(pH1, W2, out, NB, ND, NH, b2, 0);
}